// round 1
// baseline (speedup 1.0000x reference)
#include <cuda_runtime.h>

// PQCClassifier: the reference ignores x entirely (fixed |0000> state, scalar
// thetas). Output is log_softmax([cos(tx)+cos(ty), 2]) broadcast over the
// batch. Kernel = compute 2 scalars, fill out[bsz,2] with (a,b) pairs.

__global__ void pqc_fill_kernel(const float* __restrict__ theta_rx,
                                const float* __restrict__ theta_ry,
                                float4* __restrict__ out, int n4) {
    // Scalars: same address for all threads -> L1/L2 broadcast, cheap.
    float tx = *theta_rx;
    float ty = *theta_ry;
    float l0 = cosf(tx) + cosf(ty);   // <Z0> + <Z1>
    float l1 = 2.0f;                  // <Z2> + <Z3> = 1 + 1
    float m  = fmaxf(l0, l1);
    float lse = m + logf(expf(l0 - m) + expf(l1 - m));
    float a = l0 - lse;
    float b = l1 - lse;
    float4 v = make_float4(a, b, a, b);

    int idx = blockIdx.x * blockDim.x + threadIdx.x;
    int stride = gridDim.x * blockDim.x;
    for (int i = idx; i < n4; i += stride)
        out[i] = v;
}

extern "C" void kernel_launch(void* const* d_in, const int* in_sizes, int n_in,
                              void* d_out, int out_size) {
    // metadata order: x [BSZ,4] f32, theta_rx f32[1], theta_ry f32[1], theta_rz f32[1]
    const float* theta_rx = (const float*)d_in[1];
    const float* theta_ry = (const float*)d_in[2];
    // theta_rz only contributes a global phase on |0> -> no effect on probs.

    float4* out4 = (float4*)d_out;
    int n4 = out_size / 4;  // out_size = BSZ*2 floats, divisible by 4

    const int threads = 256;
    // ~4 float4 stores per thread: enough MLP to saturate store bandwidth,
    // small enough grid for one wave + fast ramp.
    int blocks = (n4 + threads * 4 - 1) / (threads * 4);
    pqc_fill_kernel<<<blocks, threads>>>(theta_rx, theta_ry, out4, n4);
}